// round 1
// baseline (speedup 1.0000x reference)
#include <cuda_runtime.h>
#include <math.h>
#include <stdint.h>

// Problem constants
#define BATCH 2048
#define LL    30
#define DD    512
#define XX    512
#define HH    4
#define OUTN  512
#define M1    (BATCH*LL)          // 61440
#define OUT2BASE ((size_t)BATCH*DD*HH)   // 4,194,304

// Scratch (device globals: no allocation allowed)
__device__ float g_hl[BATCH*OUTN];    // left @ W1l^T  (4 MB)
__device__ float g_lin[M1*HH];        // pre-softmax lin (B,L,H) (1 MB)

// ---------------------------------------------------------------------------
// GEMM kernel.
//   MODE 0: hl = A(left) @ W1[:, 0:512]^T          -> write raw to g_hl
//   MODE 1: lin = tanh(A(right)@W1[:,512:]^T + hl) @ W2^T -> write g_lin
// Tiling: BM=64 rows, BN=128 cols per n-tile, KC=32 chunks, 256 threads.
// A tile (64x512) fully resident in smem; W1 chunks register-double-buffered.
// ---------------------------------------------------------------------------
template<int MODE>
__global__ void gemm_k(const float* __restrict__ A,
                       const float* __restrict__ W1,
                       const float* __restrict__ W2)
{
    constexpr int BM = 64, BNT = 128, KC = 32;
    constexpr int ASTR = 516;   // 512 + 4 pad: row stride ≡ 4 (mod 32) -> conflict-free m-broadcast reads
    constexpr int BSTR = 132;   // 128 + 4 pad

    extern __shared__ float sm[];
    float* A_s   = sm;                       // 64*516
    float* B_s   = A_s + BM*ASTR;            // 32*132
    float* W2_s  = B_s + KC*BSTR;            // 512*4   (MODE 1 only)
    float* lin_s = W2_s + OUTN*HH;           // 64*4    (MODE 1 only)

    const int tid = threadIdx.x;
    const int tm  = tid >> 4;       // 0..15
    const int tn  = tid & 15;       // 0..15
    const int m0  = blockIdx.x * BM;
    const int koff = (MODE == 0) ? 0 : XX;

    // ---- load A tile (64 x 512) via float4, row-major into padded smem ----
    {
        const float4* Ag = (const float4*)(A + (size_t)m0 * DD);
        #pragma unroll
        for (int r = 0; r < 32; r++) {
            int idx = r * 256 + tid;          // 8192 float4 total
            int m   = idx >> 7;
            int k4  = idx & 127;
            float4 v = Ag[m * 128 + k4];
            *(float4*)&A_s[m * ASTR + k4 * 4] = v;
        }
    }
    if (MODE == 1) {
        for (int idx = tid; idx < OUTN * HH; idx += 256) {
            int h = idx >> 9, o = idx & 511;
            W2_s[o * 4 + h] = W2[idx];        // transpose to [o][h]
        }
        if (tid < BM * HH) lin_s[tid] = 0.f;
    }

    float acc[4][8];
    #pragma unroll
    for (int i = 0; i < 4; i++)
        #pragma unroll
        for (int j = 0; j < 8; j++) acc[i][j] = 0.f;

    const int nt0 = (MODE == 0) ? blockIdx.y : 0;
    const int totalChunks = (MODE == 0) ? 16 : 64;

    // prefetch chunk 0 into registers
    float rB[16];
    {
        int nbase = ((MODE == 0) ? nt0 : 0) * BNT;
        #pragma unroll
        for (int r = 0; r < 16; r++) {
            int idx = r * 256 + tid;
            int o = idx >> 5, k = idx & 31;
            rB[r] = __ldg(&W1[(size_t)(nbase + o) * 1024 + koff + k]);
        }
    }

    for (int c = 0; c < totalChunks; c++) {
        __syncthreads();
        // store register buffer to B_s transposed [k][o]
        #pragma unroll
        for (int r = 0; r < 16; r++) {
            int idx = r * 256 + tid;
            int o = idx >> 5, k = idx & 31;
            B_s[k * BSTR + o] = rB[r];
        }
        __syncthreads();
        // prefetch next chunk
        if (c + 1 < totalChunks) {
            int nc = c + 1;
            int nt = (MODE == 0) ? nt0 : (nc >> 4);
            int kb = (nc & 15) * KC;
            int nbase = nt * BNT;
            #pragma unroll
            for (int r = 0; r < 16; r++) {
                int idx = r * 256 + tid;
                int o = idx >> 5, k = idx & 31;
                rB[r] = __ldg(&W1[(size_t)(nbase + o) * 1024 + koff + kb + k]);
            }
        }
        const int kbase = ((MODE == 0) ? c : (c & 15)) * KC;
        #pragma unroll 8
        for (int k = 0; k < KC; k++) {
            int ka = kbase + k;
            float aa[4];
            aa[0] = A_s[(tm * 4 + 0) * ASTR + ka];
            aa[1] = A_s[(tm * 4 + 1) * ASTR + ka];
            aa[2] = A_s[(tm * 4 + 2) * ASTR + ka];
            aa[3] = A_s[(tm * 4 + 3) * ASTR + ka];
            float4 b0 = *(const float4*)&B_s[k * BSTR + tn * 8];
            float4 b1 = *(const float4*)&B_s[k * BSTR + tn * 8 + 4];
            float bb[8] = {b0.x, b0.y, b0.z, b0.w, b1.x, b1.y, b1.z, b1.w};
            #pragma unroll
            for (int i = 0; i < 4; i++)
                #pragma unroll
                for (int j = 0; j < 8; j++)
                    acc[i][j] += aa[i] * bb[j];
        }

        const bool endTile = (MODE == 0) ? (c == 15) : ((c & 15) == 15);
        if (endTile) {
            const int nt = (MODE == 0) ? nt0 : (c >> 4);
            const int nbase = nt * BNT;
            if (MODE == 0) {
                #pragma unroll
                for (int i = 0; i < 4; i++) {
                    int m = m0 + tm * 4 + i;
                    float* dst = &g_hl[(size_t)m * OUTN + nbase + tn * 8];
                    *(float4*)dst       = make_float4(acc[i][0], acc[i][1], acc[i][2], acc[i][3]);
                    *(float4*)(dst + 4) = make_float4(acc[i][4], acc[i][5], acc[i][6], acc[i][7]);
                }
            } else {
                float part[4][4];
                #pragma unroll
                for (int i = 0; i < 4; i++)
                    #pragma unroll
                    for (int h = 0; h < 4; h++) part[i][h] = 0.f;

                #pragma unroll
                for (int i = 0; i < 4; i++) {
                    int m = m0 + tm * 4 + i;
                    int bidx = m / LL;
                    const float* hlr = &g_hl[(size_t)bidx * OUTN + nbase + tn * 8];
                    #pragma unroll
                    for (int j = 0; j < 8; j++) {
                        int o = nbase + tn * 8 + j;
                        float t = tanhf(acc[i][j] + __ldg(&hlr[j]));
                        float4 w = *(const float4*)&W2_s[o * 4];
                        part[i][0] += w.x * t;
                        part[i][1] += w.y * t;
                        part[i][2] += w.z * t;
                        part[i][3] += w.w * t;
                    }
                }
                // deterministic reduce over the 16 tn-lanes (width-16 groups)
                #pragma unroll
                for (int i = 0; i < 4; i++)
                    #pragma unroll
                    for (int h = 0; h < 4; h++) {
                        float v = part[i][h];
                        v += __shfl_down_sync(0xffffffffu, v, 8, 16);
                        v += __shfl_down_sync(0xffffffffu, v, 4, 16);
                        v += __shfl_down_sync(0xffffffffu, v, 2, 16);
                        v += __shfl_down_sync(0xffffffffu, v, 1, 16);
                        if (tn == 0) lin_s[(tm * 4 + i) * 4 + h] += v;
                    }
                #pragma unroll
                for (int i = 0; i < 4; i++)
                    #pragma unroll
                    for (int j = 0; j < 8; j++) acc[i][j] = 0.f;
            }
        }
    }

    if (MODE == 1) {
        __syncthreads();
        if (tid < BM * HH) {
            int m = m0 + (tid >> 2);
            g_lin[(size_t)m * HH + (tid & 3)] = lin_s[tid];
        }
    }
}

// ---------------------------------------------------------------------------
// K2: per-batch block. Gram once, 4 cheap iterations, evd_cred, softmax,
// AoA GLU, attended + both outputs.
// ---------------------------------------------------------------------------
__global__ void k2_kernel(const float* __restrict__ right, const int* __restrict__ mask,
                          const float* __restrict__ Wo, const float* __restrict__ bo,
                          const float* __restrict__ scales, const float* __restrict__ Wc,
                          const float* __restrict__ bc, const float* __restrict__ sfin,
                          const float* __restrict__ Waoa, const float* __restrict__ baoa,
                          float* __restrict__ out)
{
    extern __shared__ float sm[];
    float* R     = sm;             // 30*512 = 15360
    float* G     = R + LL * DD;    // 900
    float* sv    = G + 900;        // 30
    float* credv = sv + 30;        // 30
    float* evd   = credv + 30;     // 120
    float* awb   = evd + 120;      // 120
    float* gb    = awb + 120;      // 240
    float* aw2s  = gb + 240;       // 120
    __shared__ int validsh;

    const int b = blockIdx.x;
    const int tid = threadIdx.x;
    const int warp = tid >> 5, lane = tid & 31;

    // load right[b] (30x512)
    {
        const float4* Rg = (const float4*)(right + (size_t)b * LL * DD);
        float4* R4 = (float4*)R;
        for (int idx = tid; idx < LL * DD / 4; idx += 256) R4[idx] = Rg[idx];
    }
    if (tid == 0) {
        int v = 0;
        for (int l = 0; l < LL; l++) v += mask[b * LL + l];
        validsh = v;
    }
    __syncthreads();

    // ---- Gram matrix G[q,k] = (right_q . right_k) / sqrt(D), symmetric ----
    const float inv_sqrt_d = 0.04419417382415922f;   // 1/sqrt(512)
    for (int p = warp; p < 465; p += 8) {
        int q = 0, rem = p;
        while (rem >= LL - q) { rem -= LL - q; q++; }
        int kk = q + rem;
        const float4* Rq = (const float4*)(R + q * DD);
        const float4* Rk = (const float4*)(R + kk * DD);
        float ssum = 0.f;
        for (int d = lane; d < 128; d += 32) {
            float4 x = Rq[d], y = Rk[d];
            ssum += x.x * y.x + x.y * y.y + x.z * y.z + x.w * y.w;
        }
        for (int off = 16; off > 0; off >>= 1)
            ssum += __shfl_down_sync(0xffffffffu, ssum, off);
        if (lane == 0) {
            float gv = ssum * inv_sqrt_d;
            G[q * LL + kk] = gv;
            if (kk != q) G[kk * LL + q] = gv;
        }
    }
    if (tid < LL) sv[tid] = 1.f;
    __syncthreads();

    // ---- iterative credibility blocks (warp 0 only; scores = G * s[k]) ----
    if (warp == 0) {
        const int valid = validsh;
        const float validf = (float)valid;
        for (int it = 0; it < 4; it++) {
            float scale = scales[it];
            if (lane < LL) {
                const float* Grow = G + lane * LL;
                float credq = 0.f;
                for (int k = 0; k < valid; k++) credq += Grow[k] * sv[k];
                credv[lane] = credq * scale / validf;
            }
            __syncwarp();
            float xbv = 0.f;
            if (lane < LL) {
                const float* Wrow = Wo + it * LL * LL + lane * LL;
                float z = bo[it * LL + lane];
                for (int j = 0; j < LL; j++) z += Wrow[j] * credv[j];
                xbv = tanhf(expf(z));
            }
            __syncwarp();
            if (lane < LL) sv[lane] = xbv;
            __syncwarp();
        }
    }
    __syncthreads();

    // ---- final evd_cred (unmasked keys) ----
    const float sf = *sfin;
    if (tid < LL * HH) {
        int q = tid >> 2, h = tid & 3;
        const float* Grow = G + q * LL;
        float z = 0.f;
        for (int k = 0; k < LL; k++) z += Grow[k] * sv[k] * Wc[h * LL + k];
        z = z * sf + bc[h];
        evd[tid] = tanhf(expf(z));
    }

    // ---- masked softmax over L per head (warps 0..3) ----
    if (warp < HH) {
        int h = warp;
        int mk = 0;
        float v = -3.4e38f;
        if (lane < LL) {
            mk = mask[b * LL + lane];
            if (mk) v = g_lin[((size_t)b * LL + lane) * HH + h];
        }
        float mx = v;
        for (int off = 16; off > 0; off >>= 1)
            mx = fmaxf(mx, __shfl_xor_sync(0xffffffffu, mx, off));
        float e = (lane < LL && mk) ? expf(v - mx) : 0.f;
        float s = e;
        for (int off = 16; off > 0; off >>= 1)
            s += __shfl_xor_sync(0xffffffffu, s, off);
        if (lane < LL) awb[lane * HH + h] = e / s;
    }
    __syncthreads();

    // ---- AoA GLU: g = [aw, evd] @ Waoa^T + b ----
    if (tid < LL * 2 * HH) {
        int l = tid >> 3, j = tid & 7;
        float g = baoa[j];
        const float* Wr = Waoa + j * 2 * HH;
        #pragma unroll
        for (int j2 = 0; j2 < HH; j2++) g += Wr[j2] * awb[l * HH + j2];
        #pragma unroll
        for (int j2 = 0; j2 < HH; j2++) g += Wr[HH + j2] * evd[l * HH + j2];
        gb[tid] = g;
    }
    __syncthreads();
    if (tid < LL * HH) {
        int l = tid >> 2, h = tid & 3;
        float a = gb[l * 8 + h], bbv = gb[l * 8 + 4 + h];
        aw2s[tid] = a / (1.f + expf(-bbv));
    }
    __syncthreads();

    // ---- output 2: concat([evd_cred, aw2]) -> (B, L, 8) ----
    if (tid < LL * 2 * HH) {
        int l = tid >> 3, c = tid & 7;
        float v = (c < 4) ? evd[l * 4 + c] : aw2s[l * 4 + (c - 4)];
        out[OUT2BASE + (size_t)b * (LL * 2 * HH) + tid] = v;
    }

    // ---- attended[b,d,h] = sum_l R[l,d]*aw2[l,h]; thread: 2 d x 4 h ----
    float accA[8];
    #pragma unroll
    for (int i = 0; i < 8; i++) accA[i] = 0.f;
    const int d0 = tid * 2;
    #pragma unroll 5
    for (int l = 0; l < LL; l++) {
        float r0 = R[l * DD + d0];
        float r1 = R[l * DD + d0 + 1];
        float4 w = *(const float4*)&aw2s[l * 4];
        accA[0] += r0 * w.x; accA[1] += r0 * w.y; accA[2] += r0 * w.z; accA[3] += r0 * w.w;
        accA[4] += r1 * w.x; accA[5] += r1 * w.y; accA[6] += r1 * w.z; accA[7] += r1 * w.w;
    }
    float* od = out + (size_t)b * DD * HH + tid * 8;
    *(float4*)od       = make_float4(accA[0], accA[1], accA[2], accA[3]);
    *(float4*)(od + 4) = make_float4(accA[4], accA[5], accA[6], accA[7]);
}

// ---------------------------------------------------------------------------
extern "C" void kernel_launch(void* const* d_in, const int* in_sizes, int n_in,
                              void* d_out, int out_size)
{
    const float* left   = (const float*)d_in[0];
    const float* right  = (const float*)d_in[1];
    const int*   mask   = (const int*)  d_in[2];
    const float* W1     = (const float*)d_in[3];
    const float* W2     = (const float*)d_in[4];
    const float* W_o    = (const float*)d_in[5];
    const float* b_o    = (const float*)d_in[6];
    const float* scales = (const float*)d_in[7];
    const float* W_c    = (const float*)d_in[8];
    const float* b_c    = (const float*)d_in[9];
    const float* sfin   = (const float*)d_in[10];
    const float* W_aoa  = (const float*)d_in[11];
    const float* b_aoa  = (const float*)d_in[12];
    float* out = (float*)d_out;

    const int SMEM0 = (64 * 516 + 32 * 132) * 4;                       // 148,992
    const int SMEM1 = (64 * 516 + 32 * 132 + 512 * 4 + 64 * 4) * 4;   // 158,208
    const int SMEM2 = (30 * 512 + 900 + 30 + 30 + 120 + 120 + 240 + 120) * 4; // 67,680

    cudaFuncSetAttribute(gemm_k<0>, cudaFuncAttributeMaxDynamicSharedMemorySize, SMEM0);
    cudaFuncSetAttribute(gemm_k<1>, cudaFuncAttributeMaxDynamicSharedMemorySize, SMEM1);
    cudaFuncSetAttribute(k2_kernel, cudaFuncAttributeMaxDynamicSharedMemorySize, SMEM2);

    // K0: hl = left @ W1l^T   (grid: 2048/64 M-tiles x 4 N-tiles)
    gemm_k<0><<<dim3(32, 4), 256, SMEM0>>>(left, W1, nullptr);
    // K1: fused lin GEMM over 61440 rows (960 M-tiles)
    gemm_k<1><<<dim3(960, 1), 256, SMEM1>>>(right, W1, W2);
    // K2: per-batch epilogue
    k2_kernel<<<BATCH, 256, SMEM2>>>(right, mask, W_o, b_o, scales, W_c, b_c,
                                     sfin, W_aoa, b_aoa, out);
}

// round 4
// speedup vs baseline: 2.8012x; 2.8012x over previous
#include <cuda_runtime.h>
#include <cuda_bf16.h>
#include <math.h>
#include <stdint.h>

// Problem constants
#define BATCH 2048
#define LL    30
#define DD    512
#define XX    512
#define HH    4
#define OUTN  512
#define M1    (BATCH*LL)                 // 61440
#define OUT2BASE ((size_t)BATCH*DD*HH)   // 4,194,304

// Scratch (device globals: no allocation allowed)
__device__ float    g_hl[BATCH*OUTN];    // left @ W1l^T  (4 MB)
__device__ float    g_lin[M1*HH];        // pre-softmax lin (1 MB)
// W1 repacked into mma.sync B-fragment layout, bf16 hi/lo (2 MB):
// index = ((((half*32 + ktg)*64 + nt)*2 + t_hl)*2 + r)*32 + lane
__device__ uint32_t g_W1c[524288];

// ---------------------------------------------------------------------------
// fp32 -> (bf16 hi, bf16 lo) packed pair
__device__ __forceinline__ void pack_hilo(float f0, float f1, uint32_t& hi, uint32_t& lo) {
    __nv_bfloat16 h0 = __float2bfloat16(f0);
    __nv_bfloat16 h1 = __float2bfloat16(f1);
    __nv_bfloat16 l0 = __float2bfloat16(f0 - __bfloat162float(h0));
    __nv_bfloat16 l1 = __float2bfloat16(f1 - __bfloat162float(h1));
    unsigned short uh0 = *(unsigned short*)&h0, uh1 = *(unsigned short*)&h1;
    unsigned short ul0 = *(unsigned short*)&l0, ul1 = *(unsigned short*)&l1;
    hi = (uint32_t)uh0 | ((uint32_t)uh1 << 16);
    lo = (uint32_t)ul0 | ((uint32_t)ul1 << 16);
}

// warp-level bf16 mma, fp32 accumulate (portable: sm_80+, compiles at compute_100)
#define MMA_BF16(c, a, b0, b1)                                                  \
    asm volatile("mma.sync.aligned.m16n8k16.row.col.f32.bf16.bf16.f32 "         \
        "{%0,%1,%2,%3}, {%4,%5,%6,%7}, {%8,%9}, {%0,%1,%2,%3};"                 \
        : "+f"((c)[0]), "+f"((c)[1]), "+f"((c)[2]), "+f"((c)[3])                \
        : "r"((a)[0]), "r"((a)[1]), "r"((a)[2]), "r"((a)[3]), "r"(b0), "r"(b1))

// ---------------------------------------------------------------------------
// Pre-pass: repack W1 (512 x 1024 fp32) into g_W1c fragment layout.
// B-frag (m16n8k16 .col): lane l: n = nt*8 + l/4 ; k = ktg*16 + 2*(l%4) + 8*r (+0,+1)
// ---------------------------------------------------------------------------
__global__ void prep_w1(const float* __restrict__ W1) {
    int i = blockIdx.x * blockDim.x + threadIdx.x;   // 262144 total
    int lane = i & 31;
    int r    = (i >> 5) & 1;
    int nt   = (i >> 6) & 63;
    int ktg  = (i >> 12) & 31;
    int half = (i >> 17) & 1;
    int n  = nt * 8 + (lane >> 2);
    int kk = ktg * 16 + (lane & 3) * 2 + r * 8;
    int col = half * 512 + kk;
    float f0 = __ldg(&W1[(size_t)n * 1024 + col]);
    float f1 = __ldg(&W1[(size_t)n * 1024 + col + 1]);
    uint32_t hi, lo; pack_hilo(f0, f1, hi, lo);
    uint32_t base = ((((uint32_t)half * 32 + ktg) * 64 + nt) * 2) * 2 * 32 + r * 32 + lane;
    g_W1c[base]      = hi;        // t_hl = 0
    g_W1c[base + 64] = lo;        // t_hl = 1
}

// ---------------------------------------------------------------------------
// SMEM offsets (bytes) for the GEMM kernel
#define SO_AHI 0                  // bf16[64][72]  = 9216
#define SO_ALO 9216               // bf16[64][72]  = 9216
#define SO_W2  18432              // fp32[512*4]   = 8192   (MODE 1)
#define SO_HL  26624              // fp32[4*512]   = 8192   (MODE 1)
#define SO_RED 34816              // fp32[16][64][4] = 16384 (MODE 1)
#define SMEM_GEMM_BYTES 51200
#define ASTR_U32 36               // A_s row stride in u32 (72 bf16)

// ---------------------------------------------------------------------------
// Tensor-core GEMM via mma.sync (bf16 hi/lo 3-term split, fp32 accumulate).
//   MODE 0: g_hl  = left  @ W1[:, 0:512]^T                  (M = 2048)
//   MODE 1: g_lin = tanh(right @ W1[:,512:]^T + hl) @ W2^T  (M = 61440)
// CTA: BM=64 rows x BN=512 cols, 512 threads (16 warps), warp tile 64x32.
// K chunks of 64 (4 k-tiles of 16).
// ---------------------------------------------------------------------------
template<int MODE>
__global__ void __launch_bounds__(512, 1)
tc_gemm(const float* __restrict__ A, const float* __restrict__ W2)
{
    extern __shared__ __align__(16) char smem[];
    uint32_t* auh = (uint32_t*)(smem + SO_AHI);
    uint32_t* aul = (uint32_t*)(smem + SO_ALO);

    const int tid  = threadIdx.x;
    const int wid  = tid >> 5;
    const int lane = tid & 31;
    const int g    = lane >> 2;      // 0..7
    const int t4   = lane & 3;       // 0..3
    const int m0   = blockIdx.x * 64;
    const int half = MODE;           // W1 column half

    int b0 = 0;
    if (MODE == 1) {
        float* W2s = (float*)(smem + SO_W2);
        for (int idx = tid; idx < OUTN * HH; idx += 512) {
            int o = idx >> 2, h = idx & 3;
            W2s[o * 4 + h] = __ldg(&W2[h * OUTN + o]);
        }
        b0 = m0 / LL;
        int b1 = (m0 + 63) / LL;
        int n4 = (b1 - b0 + 1) * (OUTN / 4);
        float4* hls = (float4*)(smem + SO_HL);
        const float4* src = (const float4*)(g_hl + (size_t)b0 * OUTN);
        for (int idx = tid; idx < n4; idx += 512) hls[idx] = src[idx];
    }

    float acc[4][4][4];   // [mi][j][c]
    #pragma unroll
    for (int mi = 0; mi < 4; mi++)
        #pragma unroll
        for (int j = 0; j < 4; j++)
            #pragma unroll
            for (int c = 0; c < 4; c++) acc[mi][j][c] = 0.f;

    // A staging mapping: row = tid/8, 8 floats at col (tid%8)*8
    const int arow = tid >> 3;
    const int acg  = tid & 7;
    const float4* aptr = (const float4*)(A + (size_t)(m0 + arow) * DD + acg * 8);

    float4 v0 = __ldg(&aptr[0]);
    float4 v1 = __ldg(&aptr[1]);

    for (int kc = 0; kc < 8; kc++) {
        // ---- stage A chunk: convert to bf16 hi/lo ----
        {
            uint4 hi, lo;
            pack_hilo(v0.x, v0.y, hi.x, lo.x);
            pack_hilo(v0.z, v0.w, hi.y, lo.y);
            pack_hilo(v1.x, v1.y, hi.z, lo.z);
            pack_hilo(v1.z, v1.w, hi.w, lo.w);
            uint32_t off = (uint32_t)arow * ASTR_U32 + acg * 4;
            *(uint4*)&auh[off] = hi;
            *(uint4*)&aul[off] = lo;
        }
        __syncthreads();
        // prefetch next chunk
        if (kc < 7) {
            v0 = __ldg(&aptr[(kc + 1) * 16]);
            v1 = __ldg(&aptr[(kc + 1) * 16 + 1]);
        }

        // ---- compute: 4 k-tiles ----
        #pragma unroll
        for (int kt = 0; kt < 4; kt++) {
            const int cb = kt * 8;
            const int ktg = kc * 4 + kt;
            const uint32_t* bp = g_W1c + (uint32_t)half * 262144 + (uint32_t)ktg * 8192
                                 + (uint32_t)(wid * 4) * 128 + lane;
            // B fragments held in registers across both A terms
            uint32_t bh0[4], bh1[4], bl0[4], bl1[4];
            #pragma unroll
            for (int j = 0; j < 4; j++) {
                bh0[j] = __ldg(&bp[j * 128]);
                bh1[j] = __ldg(&bp[j * 128 + 32]);
                bl0[j] = __ldg(&bp[j * 128 + 64]);
                bl1[j] = __ldg(&bp[j * 128 + 96]);
            }
            uint32_t a[4][4];
            #pragma unroll
            for (int mi = 0; mi < 4; mi++) {
                int r0 = (mi * 16 + g) * ASTR_U32 + cb + t4;
                a[mi][0] = auh[r0];
                a[mi][1] = auh[r0 + 8 * ASTR_U32];
                a[mi][2] = auh[r0 + 4];
                a[mi][3] = auh[r0 + 8 * ASTR_U32 + 4];
            }
            #pragma unroll
            for (int j = 0; j < 4; j++) {
                #pragma unroll
                for (int mi = 0; mi < 4; mi++) MMA_BF16(acc[mi][j], a[mi], bh0[j], bh1[j]);
                #pragma unroll
                for (int mi = 0; mi < 4; mi++) MMA_BF16(acc[mi][j], a[mi], bl0[j], bl1[j]);
            }
            // A-lo term x B-hi
            #pragma unroll
            for (int mi = 0; mi < 4; mi++) {
                int r0 = (mi * 16 + g) * ASTR_U32 + cb + t4;
                a[mi][0] = aul[r0];
                a[mi][1] = aul[r0 + 8 * ASTR_U32];
                a[mi][2] = aul[r0 + 4];
                a[mi][3] = aul[r0 + 8 * ASTR_U32 + 4];
            }
            #pragma unroll
            for (int j = 0; j < 4; j++) {
                #pragma unroll
                for (int mi = 0; mi < 4; mi++) MMA_BF16(acc[mi][j], a[mi], bh0[j], bh1[j]);
            }
        }
        __syncthreads();
    }

    // ---- epilogue ----
    if (MODE == 0) {
        #pragma unroll
        for (int mi = 0; mi < 4; mi++) {
            #pragma unroll
            for (int j = 0; j < 4; j++) {
                int col = wid * 32 + j * 8 + 2 * t4;
                int r0 = m0 + mi * 16 + g;
                *(float2*)&g_hl[(size_t)r0 * OUTN + col] =
                    make_float2(acc[mi][j][0], acc[mi][j][1]);
                *(float2*)&g_hl[(size_t)(r0 + 8) * OUTN + col] =
                    make_float2(acc[mi][j][2], acc[mi][j][3]);
            }
        }
    } else {
        const float* W2s = (const float*)(smem + SO_W2);
        const float* hls = (const float*)(smem + SO_HL);
        float* red = (float*)(smem + SO_RED);
        #pragma unroll
        for (int mi = 0; mi < 4; mi++) {
            #pragma unroll
            for (int hm = 0; hm < 2; hm++) {
                int rowl = mi * 16 + g + 8 * hm;
                int gm = m0 + rowl;
                const float* hlr = hls + (size_t)(gm / LL - b0) * OUTN;
                float p0 = 0.f, p1 = 0.f, p2 = 0.f, p3 = 0.f;
                #pragma unroll
                for (int j = 0; j < 4; j++) {
                    int o0 = wid * 32 + j * 8 + 2 * t4;
                    float t0 = tanhf(acc[mi][j][hm * 2 + 0] + hlr[o0]);
                    float t1 = tanhf(acc[mi][j][hm * 2 + 1] + hlr[o0 + 1]);
                    float4 w0 = *(const float4*)&W2s[o0 * 4];
                    float4 w1 = *(const float4*)&W2s[(o0 + 1) * 4];
                    p0 += t0 * w0.x + t1 * w1.x;
                    p1 += t0 * w0.y + t1 * w1.y;
                    p2 += t0 * w0.z + t1 * w1.z;
                    p3 += t0 * w0.w + t1 * w1.w;
                }
                // deterministic reduce over the 4 t4-lanes of this row
                #pragma unroll
                for (int off = 1; off <= 2; off <<= 1) {
                    p0 += __shfl_xor_sync(0xffffffffu, p0, off);
                    p1 += __shfl_xor_sync(0xffffffffu, p1, off);
                    p2 += __shfl_xor_sync(0xffffffffu, p2, off);
                    p3 += __shfl_xor_sync(0xffffffffu, p3, off);
                }
                if (t4 == 0)
                    *(float4*)&red[wid * 256 + rowl * 4] = make_float4(p0, p1, p2, p3);
            }
        }
        __syncthreads();
        if (tid < 256) {
            float s = 0.f;
            #pragma unroll
            for (int w = 0; w < 16; w++) s += red[w * 256 + tid];
            g_lin[(size_t)(m0 + (tid >> 2)) * HH + (tid & 3)] = s;
        }
    }
}

// ---------------------------------------------------------------------------
// K2: per-batch block. Gram once, 4 cheap iterations, evd_cred, softmax,
// AoA GLU, attended + both outputs. (unchanged from the passing round)
// ---------------------------------------------------------------------------
__global__ void k2_kernel(const float* __restrict__ right, const int* __restrict__ mask,
                          const float* __restrict__ Wo, const float* __restrict__ bo,
                          const float* __restrict__ scales, const float* __restrict__ Wc,
                          const float* __restrict__ bc, const float* __restrict__ sfin,
                          const float* __restrict__ Waoa, const float* __restrict__ baoa,
                          float* __restrict__ out)
{
    extern __shared__ float sm[];
    float* R     = sm;             // 30*512
    float* G     = R + LL * DD;    // 900
    float* sv    = G + 900;        // 30
    float* credv = sv + 30;        // 30
    float* evd   = credv + 30;     // 120
    float* awb   = evd + 120;      // 120
    float* gb    = awb + 120;      // 240
    float* aw2s  = gb + 240;       // 120
    __shared__ int validsh;

    const int b = blockIdx.x;
    const int tid = threadIdx.x;
    const int warp = tid >> 5, lane = tid & 31;

    {
        const float4* Rg = (const float4*)(right + (size_t)b * LL * DD);
        float4* R4 = (float4*)R;
        for (int idx = tid; idx < LL * DD / 4; idx += 256) R4[idx] = Rg[idx];
    }
    if (tid == 0) {
        int v = 0;
        for (int l = 0; l < LL; l++) v += mask[b * LL + l];
        validsh = v;
    }
    __syncthreads();

    const float inv_sqrt_d = 0.04419417382415922f;   // 1/sqrt(512)
    for (int p = warp; p < 465; p += 8) {
        int q = 0, rem = p;
        while (rem >= LL - q) { rem -= LL - q; q++; }
        int kk = q + rem;
        const float4* Rq = (const float4*)(R + q * DD);
        const float4* Rk = (const float4*)(R + kk * DD);
        float ssum = 0.f;
        for (int d = lane; d < 128; d += 32) {
            float4 x = Rq[d], y = Rk[d];
            ssum += x.x * y.x + x.y * y.y + x.z * y.z + x.w * y.w;
        }
        for (int off = 16; off > 0; off >>= 1)
            ssum += __shfl_down_sync(0xffffffffu, ssum, off);
        if (lane == 0) {
            float gv = ssum * inv_sqrt_d;
            G[q * LL + kk] = gv;
            if (kk != q) G[kk * LL + q] = gv;
        }
    }
    if (tid < LL) sv[tid] = 1.f;
    __syncthreads();

    if (warp == 0) {
        const int valid = validsh;
        const float validf = (float)valid;
        for (int it = 0; it < 4; it++) {
            float scale = scales[it];
            if (lane < LL) {
                const float* Grow = G + lane * LL;
                float credq = 0.f;
                for (int k = 0; k < valid; k++) credq += Grow[k] * sv[k];
                credv[lane] = credq * scale / validf;
            }
            __syncwarp();
            float xbv = 0.f;
            if (lane < LL) {
                const float* Wrow = Wo + it * LL * LL + lane * LL;
                float z = bo[it * LL + lane];
                for (int j = 0; j < LL; j++) z += Wrow[j] * credv[j];
                xbv = tanhf(expf(z));
            }
            __syncwarp();
            if (lane < LL) sv[lane] = xbv;
            __syncwarp();
        }
    }
    __syncthreads();

    const float sf = *sfin;
    if (tid < LL * HH) {
        int q = tid >> 2, h = tid & 3;
        const float* Grow = G + q * LL;
        float z = 0.f;
        for (int k = 0; k < LL; k++) z += Grow[k] * sv[k] * Wc[h * LL + k];
        z = z * sf + bc[h];
        evd[tid] = tanhf(expf(z));
    }

    if (warp < HH) {
        int h = warp;
        int mk = 0;
        float v = -3.4e38f;
        if (lane < LL) {
            mk = mask[b * LL + lane];
            if (mk) v = g_lin[((size_t)b * LL + lane) * HH + h];
        }
        float mx = v;
        for (int off = 16; off > 0; off >>= 1)
            mx = fmaxf(mx, __shfl_xor_sync(0xffffffffu, mx, off));
        float e = (lane < LL && mk) ? expf(v - mx) : 0.f;
        float s = e;
        for (int off = 16; off > 0; off >>= 1)
            s += __shfl_xor_sync(0xffffffffu, s, off);
        if (lane < LL) awb[lane * HH + h] = e / s;
    }
    __syncthreads();

    if (tid < LL * 2 * HH) {
        int l = tid >> 3, j = tid & 7;
        float g = baoa[j];
        const float* Wr = Waoa + j * 2 * HH;
        #pragma unroll
        for (int j2 = 0; j2 < HH; j2++) g += Wr[j2] * awb[l * HH + j2];
        #pragma unroll
        for (int j2 = 0; j2 < HH; j2++) g += Wr[HH + j2] * evd[l * HH + j2];
        gb[tid] = g;
    }
    __syncthreads();
    if (tid < LL * HH) {
        int l = tid >> 2, h = tid & 3;
        float a = gb[l * 8 + h], bbv = gb[l * 8 + 4 + h];
        aw2s[tid] = a / (1.f + expf(-bbv));
    }
    __syncthreads();

    if (tid < LL * 2 * HH) {
        int l = tid >> 3, c = tid & 7;
        float v = (c < 4) ? evd[l * 4 + c] : aw2s[l * 4 + (c - 4)];
        out[OUT2BASE + (size_t)b * (LL * 2 * HH) + tid] = v;
    }

    float accA[8];
    #pragma unroll
    for (int i = 0; i < 8; i++) accA[i] = 0.f;
    const int d0 = tid * 2;
    #pragma unroll 5
    for (int l = 0; l < LL; l++) {
        float r0 = R[l * DD + d0];
        float r1 = R[l * DD + d0 + 1];
        float4 w = *(const float4*)&aw2s[l * 4];
        accA[0] += r0 * w.x; accA[1] += r0 * w.y; accA[2] += r0 * w.z; accA[3] += r0 * w.w;
        accA[4] += r1 * w.x; accA[5] += r1 * w.y; accA[6] += r1 * w.z; accA[7] += r1 * w.w;
    }
    float* od = out + (size_t)b * DD * HH + tid * 8;
    *(float4*)od       = make_float4(accA[0], accA[1], accA[2], accA[3]);
    *(float4*)(od + 4) = make_float4(accA[4], accA[5], accA[6], accA[7]);
}

// ---------------------------------------------------------------------------
extern "C" void kernel_launch(void* const* d_in, const int* in_sizes, int n_in,
                              void* d_out, int out_size)
{
    const float* left   = (const float*)d_in[0];
    const float* right  = (const float*)d_in[1];
    const int*   mask   = (const int*)  d_in[2];
    const float* W1     = (const float*)d_in[3];
    const float* W2     = (const float*)d_in[4];
    const float* W_o    = (const float*)d_in[5];
    const float* b_o    = (const float*)d_in[6];
    const float* scales = (const float*)d_in[7];
    const float* W_c    = (const float*)d_in[8];
    const float* b_c    = (const float*)d_in[9];
    const float* sfin   = (const float*)d_in[10];
    const float* W_aoa  = (const float*)d_in[11];
    const float* b_aoa  = (const float*)d_in[12];
    float* out = (float*)d_out;

    const int SMEM2 = (30 * 512 + 900 + 30 + 30 + 120 + 120 + 240 + 120) * 4;

    cudaFuncSetAttribute(tc_gemm<0>, cudaFuncAttributeMaxDynamicSharedMemorySize, SMEM_GEMM_BYTES);
    cudaFuncSetAttribute(tc_gemm<1>, cudaFuncAttributeMaxDynamicSharedMemorySize, SMEM_GEMM_BYTES);
    cudaFuncSetAttribute(k2_kernel, cudaFuncAttributeMaxDynamicSharedMemorySize, SMEM2);

    // P: repack W1 into fragment-layout bf16 hi/lo
    prep_w1<<<1024, 256>>>(W1);
    // K0: hl = left @ W1l^T   (32 M-tiles of 64)
    tc_gemm<0><<<32, 512, SMEM_GEMM_BYTES>>>(left, nullptr);
    // K1: fused lin GEMM over 61440 rows (960 M-tiles of 64)
    tc_gemm<1><<<960, 512, SMEM_GEMM_BYTES>>>(right, W2);
    // K2: per-batch epilogue
    k2_kernel<<<BATCH, 256, SMEM2>>>(right, mask, W_o, b_o, scales, W_c, b_c,
                                     sfin, W_aoa, b_aoa, out);
}